// round 4
// baseline (speedup 1.0000x reference)
#include <cuda_runtime.h>

// B=32, N=64, D=512
// score[b,i,j] = (dot(s_e[b,i,j,:], W) + bias) * adj[b,i,j], adj[b,0,1]=adj[b,1,0]=0
// Only i in {0,1} consumed. Outputs (float32, flattened tuple order):
//   final_id (32,2)=64 | s_e_score (32,2,64)=4096 | flag (32)=32

#define NB 32
#define NN 64
#define ND 512
#define GRID 512
#define TPB  256   // 8 warps -> 4096 warps total, one dot product per warp

__device__ int g_done_counter = 0;   // reset to 0 by last block each launch

__global__ void
fused_kernel(const float* __restrict__ s_e,
             const float* __restrict__ adj,
             const float* __restrict__ W,
             const float* __restrict__ bias,
             float* __restrict__ out_id,
             float* __restrict__ out_score,
             float* __restrict__ out_flag) {
    int warp = threadIdx.x >> 5;
    int lane = threadIdx.x & 31;

    // ---- Phase 1: one dot product per warp (4 front-batched LDG.128) ----
    int p = blockIdx.x * 8 + warp;          // 0..4095
    int b = p >> 7;
    int i = (p >> 6) & 1;
    int j = p & 63;

    const float4* base =
        (const float4*)(s_e + ((size_t)((b * NN + i) * NN + j)) * ND);
    const float4* wv = (const float4*)W;

    float4 a0 = base[lane];
    float4 a1 = base[32 + lane];
    float4 a2 = base[64 + lane];
    float4 a3 = base[96 + lane];
    float4 w0 = wv[lane];
    float4 w1 = wv[32 + lane];
    float4 w2 = wv[64 + lane];
    float4 w3 = wv[96 + lane];

    float sum = a0.x * w0.x + a0.y * w0.y + a0.z * w0.z + a0.w * w0.w
              + a1.x * w1.x + a1.y * w1.y + a1.z * w1.z + a1.w * w1.w
              + a2.x * w2.x + a2.y * w2.y + a2.z * w2.z + a2.w * w2.w
              + a3.x * w3.x + a3.y * w3.y + a3.z * w3.z + a3.w * w3.w;
#pragma unroll
    for (int off = 16; off; off >>= 1)
        sum += __shfl_xor_sync(0xffffffffu, sum, off);

    if (lane == 0) {
        float a = adj[(b * NN + i) * NN + j];
        if ((i == 0 && j == 1) || (i == 1 && j == 0)) a = 0.f;
        out_score[(b * 2 + i) * NN + j] = (sum + __ldg(bias)) * a;
    }

    // ---- Handshake: last of 512 blocks runs the epilogue ----
    __syncthreads();
    __shared__ bool is_last;
    if (threadIdx.x == 0) {
        __threadfence();
        int prev = atomicAdd(&g_done_counter, 1);
        is_last = (prev == GRID - 1);
    }
    __syncthreads();
    if (!is_last) return;
    __threadfence();   // acquire: all scores visible

    // ---- Phase 2 (last block): 64 row argmaxes + flags, scores L2-hot ----
    __shared__ int s_ids[64];
#pragma unroll
    for (int r = 0; r < 8; ++r) {
        int row = warp * 8 + r;                        // 0..63 == b*2 + i
        const float* rp = out_score + row * NN;
        float v0 = rp[lane];
        float v1 = rp[lane + 32];
        float v; int idx;
        if (v1 > v0) { v = v1; idx = lane + 32; }
        else         { v = v0; idx = lane; }
#pragma unroll
        for (int off = 16; off; off >>= 1) {
            float ov = __shfl_xor_sync(0xffffffffu, v, off);
            int   oi = __shfl_xor_sync(0xffffffffu, idx, off);
            if (ov > v || (ov == v && oi < idx)) { v = ov; idx = oi; }
        }
        if (lane == 0) {
            s_ids[row] = idx;
            out_id[row] = (float)idx;
        }
    }
    __syncthreads();

    if (threadIdx.x < NB) {
        int sub = s_ids[threadIdx.x * 2];
        int obj = s_ids[threadIdx.x * 2 + 1];
        float f = 0.f;
        if (sub > 0 && obj > 0)      f = 3.f;
        else if (sub > 0)            f = 1.f;
        else if (obj > 0)            f = 2.f;
        out_flag[threadIdx.x] = f;
    }

    if (threadIdx.x == 0) g_done_counter = 0;          // deterministic replays
}

extern "C" void kernel_launch(void* const* d_in, const int* in_sizes, int n_in,
                              void* d_out, int out_size) {
    const float* s_e  = (const float*)d_in[0];
    const float* adj  = (const float*)d_in[1];
    const float* W    = (const float*)d_in[2];
    const float* bias = (const float*)d_in[3];

    float* out       = (float*)d_out;
    float* out_id    = out;             // 64
    float* out_score = out + 64;        // 4096
    float* out_flag  = out + 64 + 4096; // 32

    fused_kernel<<<GRID, TPB>>>(s_e, adj, W, bias, out_id, out_score, out_flag);
}

// round 5
// speedup vs baseline: 1.0756x; 1.0756x over previous
#include <cuda_runtime.h>

// B=32, N=64, D=512
// score[b,i,j] = (dot(s_e[b,i,j,:], W) + bias) * adj[b,i,j], adj[b,0,1]=adj[b,1,0]=0
// Only i in {0,1} consumed. Outputs (float32, flattened tuple order):
//   final_id (32,2)=64 | s_e_score (32,2,64)=4096 | flag (32)=32

#define NB 32
#define NN 64
#define ND 512
#define GRID 256
#define TPB  512   // 16 warps/block -> 4096 warps, one dot product per warp

// Per-row argmax slots (64) and per-batch arrival counters (32).
// Finisher thread resets them each launch -> deterministic graph replays.
__device__ unsigned long long g_slot[NB * 2] = {};
__device__ int g_arrive[NB] = {};

__global__ void
fused_kernel(const float* __restrict__ s_e,
             const float* __restrict__ adj,
             const float* __restrict__ W,
             const float* __restrict__ bias,
             float* __restrict__ out_id,
             float* __restrict__ out_score,
             float* __restrict__ out_flag) {
    int warp = threadIdx.x >> 5;
    int lane = threadIdx.x & 31;

    int p = blockIdx.x * 16 + warp;   // 0..4095  (== row*64 + j, row = b*2+i)
    int b = p >> 7;
    int i = (p >> 6) & 1;
    int j = p & 63;
    int row = p >> 6;

    // Front-batch the 4 data loads (MLP), then stage W in shared.
    const float4* base =
        (const float4*)(s_e + ((size_t)((b * NN + i) * NN + j)) * ND);
    float4 a0 = base[lane];
    float4 a1 = base[32 + lane];
    float4 a2 = base[64 + lane];
    float4 a3 = base[96 + lane];

    __shared__ float sW[ND];
    sW[threadIdx.x] = W[threadIdx.x];
    __syncthreads();

    const float4* wv = (const float4*)sW;
    float4 w0 = wv[lane], w1 = wv[32 + lane], w2 = wv[64 + lane], w3 = wv[96 + lane];

    float sum = a0.x * w0.x + a0.y * w0.y + a0.z * w0.z + a0.w * w0.w
              + a1.x * w1.x + a1.y * w1.y + a1.z * w1.z + a1.w * w1.w
              + a2.x * w2.x + a2.y * w2.y + a2.z * w2.z + a2.w * w2.w
              + a3.x * w3.x + a3.y * w3.y + a3.z * w3.z + a3.w * w3.w;
#pragma unroll
    for (int off = 16; off; off >>= 1)
        sum += __shfl_xor_sync(0xffffffffu, sum, off);

    if (lane == 0) {
        float a = adj[(b * NN + i) * NN + j];
        if ((i == 0 && j == 1) || (i == 1 && j == 0)) a = 0.f;
        float sc = (sum + __ldg(bias)) * a;
        out_score[p] = sc;

        // Packed argmax key: monotone float encoding, smaller j wins ties.
        float c = sc + 0.0f;                    // canonicalize -0 -> +0
        unsigned int bits = __float_as_uint(c);
        unsigned int ord = (bits & 0x80000000u) ? ~bits : (bits | 0x80000000u);
        unsigned long long key =
            ((unsigned long long)ord << 32) | (unsigned long long)(63 - j);
        atomicMax(&g_slot[row], key);
        __threadfence();

        int arr = atomicAdd(&g_arrive[b], 1);
        if (arr == 127) {                       // last writer for batch b
            unsigned long long k0 = atomicMax(&g_slot[b * 2], 0ULL);
            unsigned long long k1 = atomicMax(&g_slot[b * 2 + 1], 0ULL);
            int sub = 63 - (int)(k0 & 0xFFFFFFFFu);
            int obj = 63 - (int)(k1 & 0xFFFFFFFFu);
            out_id[b * 2]     = (float)sub;
            out_id[b * 2 + 1] = (float)obj;
            float f = 0.f;
            if (sub > 0 && obj > 0)      f = 3.f;
            else if (sub > 0)            f = 1.f;
            else if (obj > 0)            f = 2.f;
            out_flag[b] = f;
            // Reset for next launch (no other thread touches these now).
            g_slot[b * 2]     = 0ULL;
            g_slot[b * 2 + 1] = 0ULL;
            g_arrive[b]       = 0;
        }
    }
}

extern "C" void kernel_launch(void* const* d_in, const int* in_sizes, int n_in,
                              void* d_out, int out_size) {
    const float* s_e  = (const float*)d_in[0];
    const float* adj  = (const float*)d_in[1];
    const float* W    = (const float*)d_in[2];
    const float* bias = (const float*)d_in[3];

    float* out       = (float*)d_out;
    float* out_id    = out;             // 64
    float* out_score = out + 64;        // 4096
    float* out_flag  = out + 64 + 4096; // 32

    fused_kernel<<<GRID, TPB>>>(s_e, adj, W, bias, out_id, out_score, out_flag);
}

// round 6
// speedup vs baseline: 1.3653x; 1.2694x over previous
#include <cuda_runtime.h>

// B=32, N=64, D=512
// score[b,i,j] = (dot(s_e[b,i,j,:], W) + bias) * adj[b,i,j], adj[b,0,1]=adj[b,1,0]=0
// Only i in {0,1} consumed. Outputs (float32, flattened tuple order):
//   final_id (32,2)=64 | s_e_score (32,2,64)=4096 | flag (32)=32

#define NB 32
#define NN 64
#define ND 512
#define GRID 128
#define TPB  512   // 16 warps, 2 dot products per warp

__device__ int g_done_counter = 0;   // reset by last block each launch

__global__ void
fused_kernel(const float* __restrict__ s_e,
             const float* __restrict__ adj,
             const float* __restrict__ W,
             const float* __restrict__ bias,
             float* __restrict__ out_id,
             float* __restrict__ out_score,
             float* __restrict__ out_flag) {
    int warp = threadIdx.x >> 5;
    int lane = threadIdx.x & 31;

    // This warp's two flattened dot-product ids: p0 = row*64 + j (row = b*2+i)
    int p0 = (blockIdx.x * 16 + warp) * 2;       // 0..4094, even
    int b  = p0 >> 7;
    int i0 = (p0 >> 6) & 1;
    int j0 = p0 & 63;                            // j1 = j0+1, same row

    // ---------- FRONT-BATCH ALL LOADS (single latency exposure) ----------
    const float4* base0 =
        (const float4*)(s_e + ((size_t)((b * NN + i0) * NN + j0)) * ND);
    const float4* base1 = base0 + (ND / 4);      // j0+1, contiguous next row
    const float4* wv = (const float4*)W;

    // adj for both j's: lanes 0 and 1 fetch, broadcast later.
    float adj_mine = 0.f;
    if (lane < 2)
        adj_mine = adj[(b * NN + i0) * NN + j0 + lane];
    float bias0 = __ldg(bias);

    float4 a0 = base0[lane];
    float4 a1 = base0[32 + lane];
    float4 a2 = base0[64 + lane];
    float4 a3 = base0[96 + lane];
    float4 c0 = base1[lane];
    float4 c1 = base1[32 + lane];
    float4 c2 = base1[64 + lane];
    float4 c3 = base1[96 + lane];
    float4 w0 = wv[lane];
    float4 w1 = wv[32 + lane];
    float4 w2 = wv[64 + lane];
    float4 w3 = wv[96 + lane];

    // ---------- compute both dots ----------
    float s0 = a0.x * w0.x + a0.y * w0.y + a0.z * w0.z + a0.w * w0.w
             + a1.x * w1.x + a1.y * w1.y + a1.z * w1.z + a1.w * w1.w
             + a2.x * w2.x + a2.y * w2.y + a2.z * w2.z + a2.w * w2.w
             + a3.x * w3.x + a3.y * w3.y + a3.z * w3.z + a3.w * w3.w;
    float s1 = c0.x * w0.x + c0.y * w0.y + c0.z * w0.z + c0.w * w0.w
             + c1.x * w1.x + c1.y * w1.y + c1.z * w1.z + c1.w * w1.w
             + c2.x * w2.x + c2.y * w2.y + c2.z * w2.z + c2.w * w2.w
             + c3.x * w3.x + c3.y * w3.y + c3.z * w3.z + c3.w * w3.w;

    // Two independent butterfly chains — ILP hides shuffle latency.
#pragma unroll
    for (int off = 16; off; off >>= 1) {
        s0 += __shfl_xor_sync(0xffffffffu, s0, off);
        s1 += __shfl_xor_sync(0xffffffffu, s1, off);
    }
    // Broadcast the two adj values warp-wide.
    float adj0 = __shfl_sync(0xffffffffu, adj_mine, 0);
    float adj1 = __shfl_sync(0xffffffffu, adj_mine, 1);

    if (lane == 0) {
        // Zero the (0,1) / (1,0) entries.
        if (i0 == 0 && j0 == 0) adj1 = 0.f;          // (i=0, j=1)
        if (i0 == 1 && j0 == 0) adj0 = 0.f;          // (i=1, j=0)
        float2 sc = make_float2((s0 + bias0) * adj0, (s1 + bias0) * adj1);
        *(float2*)(out_score + p0) = sc;             // 8B aligned (p0 even)
    }

    // ---------- handshake: last block runs the epilogue ----------
    __syncthreads();
    __shared__ bool is_last;
    if (threadIdx.x == 0) {
        __threadfence();
        int prev = atomicAdd(&g_done_counter, 1);
        is_last = (prev == GRID - 1);
    }
    __syncthreads();
    if (!is_last) return;
    __threadfence();   // acquire

    // ---------- epilogue: 64 row argmaxes + flags (L2-hot) ----------
    __shared__ int s_ids[64];
#pragma unroll
    for (int r = 0; r < 4; ++r) {
        int row = warp * 4 + r;                      // 0..63 == b*2 + i
        const float* rp = out_score + row * NN;
        float v0 = rp[lane];
        float v1 = rp[lane + 32];
        float v; int idx;
        if (v1 > v0) { v = v1; idx = lane + 32; }
        else         { v = v0; idx = lane; }
#pragma unroll
        for (int off = 16; off; off >>= 1) {
            float ov = __shfl_xor_sync(0xffffffffu, v, off);
            int   oi = __shfl_xor_sync(0xffffffffu, idx, off);
            if (ov > v || (ov == v && oi < idx)) { v = ov; idx = oi; }
        }
        if (lane == 0) {
            s_ids[row] = idx;
            out_id[row] = (float)idx;
        }
    }
    __syncthreads();

    if (threadIdx.x < NB) {
        int sub = s_ids[threadIdx.x * 2];
        int obj = s_ids[threadIdx.x * 2 + 1];
        float f = 0.f;
        if (sub > 0 && obj > 0)      f = 3.f;
        else if (sub > 0)            f = 1.f;
        else if (obj > 0)            f = 2.f;
        out_flag[threadIdx.x] = f;
    }

    if (threadIdx.x == 0) g_done_counter = 0;        // deterministic replays
}

extern "C" void kernel_launch(void* const* d_in, const int* in_sizes, int n_in,
                              void* d_out, int out_size) {
    const float* s_e  = (const float*)d_in[0];
    const float* adj  = (const float*)d_in[1];
    const float* W    = (const float*)d_in[2];
    const float* bias = (const float*)d_in[3];

    float* out       = (float*)d_out;
    float* out_id    = out;             // 64
    float* out_score = out + 64;        // 4096
    float* out_flag  = out + 64 + 4096; // 32

    fused_kernel<<<GRID, TPB>>>(s_e, adj, W, bias, out_id, out_score, out_flag);
}